// round 15
// baseline (speedup 1.0000x reference)
#include <cuda_runtime.h>
#include <cuda_fp16.h>
#include <math.h>

#define BB 2
#define SS 2048
#define EE 768
#define HH 12
#define DD 64
#define MM (BB*SS)      /* 4096 rows */
#define FF (4*EE)       /* 3072 */
#define BH (BB*HH)      /* 24 */

#define BK 64           /* k halves per GEMM slab */
#define PAW 36          /* GEMM [row][k] pitch in half2 words */

/* flash (fp16) tiles */
#define FM 128
#define FK 64
#define PQW 36
#define FSTG 3

// dynamic smem sizes (bytes)
#define SM_MMH   (2*(64*PAW + 128*PAW)*4)                  /* 55296 */
#define SM_FLASH ((128*PQW + FSTG*FK*PQW + FSTG*FK*PQW)*4) /* 73728 */

// ---------------- scratch (device globals; no allocation allowed) ----------------
__device__ __half g_y  [MM*EE];
__device__ __half g_q  [MM*EE];
__device__ __half g_k  [MM*EE];
__device__ __half g_v  [MM*EE];
__device__ __half g_vt [BH*DD*SS];
__device__ __half g_ctx[MM*EE];
__device__ float  g_y2 [MM*EE];
__device__ __half g_z  [MM*EE];
__device__ __half g_h  [MM*FF];
__device__ __half g_wtq[EE*EE];
__device__ __half g_wtk[EE*EE];
__device__ __half g_wtv[EE*EE];
__device__ __half g_wto[EE*EE];
__device__ __half g_wt1[FF*EE];
__device__ __half g_wt2[EE*FF];

// ---------------- helpers ---------------------------------------------------------
__device__ __forceinline__ void mma_f16(float& c0, float& c1, float& c2, float& c3,
                                        unsigned a0, unsigned a1, unsigned a2, unsigned a3,
                                        unsigned b0, unsigned b1) {
    asm volatile(
        "mma.sync.aligned.m16n8k16.row.col.f32.f16.f16.f32 "
        "{%0,%1,%2,%3}, {%4,%5,%6,%7}, {%8,%9}, {%0,%1,%2,%3};"
        : "+f"(c0), "+f"(c1), "+f"(c2), "+f"(c3)
        : "r"(a0), "r"(a1), "r"(a2), "r"(a3), "r"(b0), "r"(b1));
}

__device__ __forceinline__ void ldsm4(unsigned& r0, unsigned& r1, unsigned& r2, unsigned& r3,
                                      unsigned a) {
    asm volatile("ldmatrix.sync.aligned.m8n8.x4.shared.b16 {%0,%1,%2,%3}, [%4];"
        : "=r"(r0), "=r"(r1), "=r"(r2), "=r"(r3) : "r"(a));
}

__device__ __forceinline__ void cp16(unsigned saddr, const void* g) {
    asm volatile("cp.async.cg.shared.global [%0], [%1], 16;" :: "r"(saddr), "l"(g));
}
__device__ __forceinline__ void cp_commit() { asm volatile("cp.async.commit_group;"); }
__device__ __forceinline__ void cp_wait0()  { asm volatile("cp.async.wait_group 0;"); }
__device__ __forceinline__ void cp_wait1()  { asm volatile("cp.async.wait_group 1;"); }
__device__ __forceinline__ void cp_wait2()  { asm volatile("cp.async.wait_group 2;"); }

// ---------------- weight convert + transpose --------------------------------------
__global__ void cvt_t4(const float* __restrict__ s0, __half* __restrict__ d0,
                       const float* __restrict__ s1, __half* __restrict__ d1,
                       const float* __restrict__ s2, __half* __restrict__ d2,
                       const float* __restrict__ s3, __half* __restrict__ d3) {
    __shared__ float t[32][33];
    const float* src; __half* dst;
    if (blockIdx.z == 0)      { src = s0; dst = d0; }
    else if (blockIdx.z == 1) { src = s1; dst = d1; }
    else if (blockIdx.z == 2) { src = s2; dst = d2; }
    else                      { src = s3; dst = d3; }
    int bx = blockIdx.x * 32;
    int by = blockIdx.y * 32;
    int x = threadIdx.x, y0 = threadIdx.y;
    #pragma unroll
    for (int i = 0; i < 32; i += 8)
        t[y0 + i][x] = src[(size_t)(by + y0 + i) * EE + bx + x];
    __syncthreads();
    #pragma unroll
    for (int i = 0; i < 32; i += 8)
        dst[(size_t)(bx + y0 + i) * EE + by + x] = __float2half(t[x][y0 + i]);
}

__global__ void cvt_tff(const float* __restrict__ w1, __half* __restrict__ wt1,
                        const float* __restrict__ w2, __half* __restrict__ wt2) {
    __shared__ float t[32][33];
    const float* src; __half* dst; int R, C;
    if (blockIdx.z == 0) { src = w1; dst = wt1; R = EE; C = FF; }
    else                 { src = w2; dst = wt2; R = FF; C = EE; }
    int bx = blockIdx.x * 32;
    int by = blockIdx.y * 32;
    if (bx >= C || by >= R) return;
    int x = threadIdx.x, y0 = threadIdx.y;
    #pragma unroll
    for (int i = 0; i < 32; i += 8)
        t[y0 + i][x] = src[(size_t)(by + y0 + i) * C + bx + x];
    __syncthreads();
    #pragma unroll
    for (int i = 0; i < 32; i += 8)
        dst[(size_t)(bx + y0 + i) * R + by + x] = __float2half(t[x][y0 + i]);
}

// ---------------- V transpose per head ---------------------------------------------
__global__ void vtrans(const __half* __restrict__ v, __half* __restrict__ vt) {
    __shared__ __half t[32][33];
    int bh = blockIdx.z;
    int b = bh / HH, h = bh % HH;
    int s0 = blockIdx.x * 32;
    int d0 = blockIdx.y * 32;
    int x = threadIdx.x, y0 = threadIdx.y;
    #pragma unroll
    for (int i = 0; i < 32; i += 8)
        t[y0 + i][x] = v[(size_t)(b * SS + s0 + y0 + i) * EE + h * DD + d0 + x];
    __syncthreads();
    #pragma unroll
    for (int i = 0; i < 32; i += 8)
        vt[(size_t)bh * DD * SS + (size_t)(d0 + y0 + i) * SS + s0 + x] = t[x][y0 + i];
}

// ---------------- LayerNorm ---------------------------------------------------------
__global__ void ln_kernel(const float* __restrict__ x, const float* __restrict__ gw,
                          const float* __restrict__ bw, __half* __restrict__ out) {
    int row = blockIdx.x;
    int t = threadIdx.x;
    int warp = t >> 5, lane = t & 31;
    __shared__ float ws1[8], ws2[8], bc[2];

    float4 xv = make_float4(0.f, 0.f, 0.f, 0.f);
    if (t < 192)
        xv = *(const float4*)(x + (size_t)row * EE + t * 4);
    float s1 = xv.x + xv.y + xv.z + xv.w;
    float s2 = xv.x*xv.x + xv.y*xv.y + xv.z*xv.z + xv.w*xv.w;
    #pragma unroll
    for (int o = 16; o > 0; o >>= 1) {
        s1 += __shfl_xor_sync(0xffffffffu, s1, o);
        s2 += __shfl_xor_sync(0xffffffffu, s2, o);
    }
    if (lane == 0) { ws1[warp] = s1; ws2[warp] = s2; }
    __syncthreads();
    if (t == 0) {
        float a = 0.f, b = 0.f;
        #pragma unroll
        for (int i = 0; i < 8; i++) { a += ws1[i]; b += ws2[i]; }
        float mean = a * (1.0f / EE);
        float var  = b * (1.0f / EE) - mean * mean;
        bc[0] = mean;
        bc[1] = rsqrtf(var + 1e-5f);
    }
    __syncthreads();
    if (t < 192) {
        float mean = bc[0], rstd = bc[1];
        float4 gv = *(const float4*)(gw + t * 4);
        float4 bv = *(const float4*)(bw + t * 4);
        float o0 = (xv.x - mean) * rstd * gv.x + bv.x;
        float o1 = (xv.y - mean) * rstd * gv.y + bv.y;
        float o2 = (xv.z - mean) * rstd * gv.z + bv.z;
        float o3 = (xv.w - mean) * rstd * gv.w + bv.w;
        __half2 h0 = __floats2half2_rn(o0, o1);
        __half2 h1 = __floats2half2_rn(o2, o3);
        uint2 pk; pk.x = *(unsigned*)&h0; pk.y = *(unsigned*)&h1;
        *(uint2*)(out + (size_t)row * EE + t * 4) = pk;
    }
}

// ---------------- fp16 GEMM core 64x128 CTA, ldmatrix fragments --------------------
template<bool GELU, bool RES, bool OUTH>
__device__ __forceinline__ void
mmh_body(const __half* __restrict__ A, const __half* __restrict__ Wt,
         const float* __restrict__ bias, const float* __restrict__ res,
         void* __restrict__ Cv, int N, int K, int row0, int col0, char* smem) {
    unsigned* As_ = (unsigned*)smem;                  // [2][64][PAW]
    unsigned* Bs_ = As_ + 2 * 64 * PAW;               // [2][128][PAW]
    unsigned sA = (unsigned)__cvta_generic_to_shared(As_);
    unsigned sB = (unsigned)__cvta_generic_to_shared(Bs_);

    int tid  = threadIdx.x;
    int warp = tid >> 5, lane = tid & 31;
    int gid  = lane >> 2, tig = lane & 3;
    int wm   = warp & 1;
    int wn   = warp >> 1;
    int arow = lane & 15;              // ldmatrix row within 16-row tile pair
    int acb  = (lane >> 4) * 4;        // ldmatrix col word offset (0 or 4)

    float acc[2][8][4];
    #pragma unroll
    for (int i = 0; i < 2; i++)
        #pragma unroll
        for (int j = 0; j < 8; j++)
            #pragma unroll
            for (int r = 0; r < 4; r++) acc[i][j][r] = 0.0f;

    int NIT = K / BK;

    auto load_st = [&](int st, int k0) {
        #pragma unroll
        for (int i = 0; i < 4; i++) {
            int slot = tid + i * 128;
            int r = slot >> 3, c = slot & 7;
            cp16(sA + (unsigned)((st*64 + r)*PAW + c * 4)*4,
                 A + (size_t)(row0 + r) * K + k0 + c * 8);
        }
        #pragma unroll
        for (int i = 0; i < 8; i++) {
            int slot = tid + i * 128;
            int r = slot >> 3, c = slot & 7;
            cp16(sB + (unsigned)((st*128 + r)*PAW + c * 4)*4,
                 Wt + (size_t)(col0 + r) * K + k0 + c * 8);
        }
        cp_commit();
    };

    load_st(0, 0);

    for (int it = 0; it < NIT; it++) {
        cp_wait0();
        __syncthreads();

        if (it + 1 < NIT) load_st((it + 1) & 1, (it + 1) * BK);

        int buf = it & 1;
        unsigned aBase = sA + (unsigned)(buf * 64 * PAW) * 4;
        unsigned bBase = sB + (unsigned)(buf * 128 * PAW) * 4;

        #pragma unroll
        for (int kk2 = 0; kk2 < 4; kk2++) {
            int kw = kk2 * 8;
            unsigned af[2][4], bf[8][2];
            #pragma unroll
            for (int mi = 0; mi < 2; mi++) {
                unsigned ad = aBase + (unsigned)((wm*32 + mi*16 + arow) * PAW + kw + acb) * 4;
                ldsm4(af[mi][0], af[mi][1], af[mi][2], af[mi][3], ad);
            }
            #pragma unroll
            for (int np = 0; np < 4; np++) {
                unsigned bd = bBase + (unsigned)((wn*64 + np*16 + arow) * PAW + kw + acb) * 4;
                ldsm4(bf[2*np][0], bf[2*np+1][0], bf[2*np][1], bf[2*np+1][1], bd);
            }
            #pragma unroll
            for (int mi = 0; mi < 2; mi++)
                #pragma unroll
                for (int ni = 0; ni < 8; ni++)
                    mma_f16(acc[mi][ni][0], acc[mi][ni][1], acc[mi][ni][2], acc[mi][ni][3],
                            af[mi][0], af[mi][1], af[mi][2], af[mi][3],
                            bf[ni][0], bf[ni][1]);
        }
    }

    #pragma unroll
    for (int mi = 0; mi < 2; mi++) {
        int r0 = row0 + wm * 32 + mi * 16 + gid;
        int r1 = r0 + 8;
        #pragma unroll
        for (int ni = 0; ni < 8; ni++) {
            int c = col0 + wn * 64 + ni * 8 + tig * 2;
            float2 b2 = *(const float2*)(bias + c);
            float v00 = acc[mi][ni][0] + b2.x;
            float v01 = acc[mi][ni][1] + b2.y;
            float v10 = acc[mi][ni][2] + b2.x;
            float v11 = acc[mi][ni][3] + b2.y;
            if (RES) {
                float2 e0 = *(const float2*)(res + (size_t)r0 * N + c);
                float2 e1 = *(const float2*)(res + (size_t)r1 * N + c);
                v00 += e0.x; v01 += e0.y; v10 += e1.x; v11 += e1.y;
            }
            if (GELU) {
                v00 = v00 * 0.5f * (1.0f + erff(v00 * 0.70710678118654752f));
                v01 = v01 * 0.5f * (1.0f + erff(v01 * 0.70710678118654752f));
                v10 = v10 * 0.5f * (1.0f + erff(v10 * 0.70710678118654752f));
                v11 = v11 * 0.5f * (1.0f + erff(v11 * 0.70710678118654752f));
            }
            if (OUTH) {
                __half2* C = (__half2*)Cv;
                C[((size_t)r0 * N + c) / 2] = __floats2half2_rn(v00, v01);
                C[((size_t)r1 * N + c) / 2] = __floats2half2_rn(v10, v11);
            } else {
                float* C = (float*)Cv;
                *(float2*)(C + (size_t)r0 * N + c) = make_float2(v00, v01);
                *(float2*)(C + (size_t)r1 * N + c) = make_float2(v10, v11);
            }
        }
    }
}

template<bool GELU, bool RES, bool OUTH>
__global__ void __launch_bounds__(128, 3)
mmh_tc(const __half* __restrict__ A, const __half* __restrict__ Wt,
       const float* __restrict__ bias, const float* __restrict__ res,
       void* __restrict__ C, int N, int K) {
    extern __shared__ char smem[];
    mmh_body<GELU, RES, OUTH>(A, Wt, bias, res, C, N, K,
                              blockIdx.y * 64, blockIdx.x * 128, smem);
}

__global__ void __launch_bounds__(128, 3)
qkvh_tc(const __half* __restrict__ y,
        const __half* __restrict__ wtq, const float* __restrict__ bq, __half* __restrict__ q,
        const __half* __restrict__ wtk, const float* __restrict__ bk, __half* __restrict__ k,
        const __half* __restrict__ wtv, const float* __restrict__ bv, __half* __restrict__ v) {
    extern __shared__ char smem[];
    const __half* Wt; const float* bias; __half* C;
    if (blockIdx.z == 0)      { Wt = wtq; bias = bq; C = q; }
    else if (blockIdx.z == 1) { Wt = wtk; bias = bk; C = k; }
    else                      { Wt = wtv; bias = bv; C = v; }
    mmh_body<false, false, true>(y, Wt, bias, nullptr, C, EE, EE,
                                 blockIdx.y * 64, blockIdx.x * 128, smem);
}

// ---------------- Flash attention, fp16 MMA + ldmatrix ------------------------------
__global__ void __launch_bounds__(256, 2)
flash_h(const __half* __restrict__ q, const __half* __restrict__ k,
        const __half* __restrict__ vt, __half* __restrict__ ctx) {
    extern __shared__ char smem[];
    unsigned* Qw = (unsigned*)smem;
    unsigned* Kw = Qw + 128 * PQW;
    unsigned* Vw = Kw + FSTG * FK * PQW;
    unsigned sQ = (unsigned)__cvta_generic_to_shared(Qw);
    unsigned sK = (unsigned)__cvta_generic_to_shared(Kw);
    unsigned sV = (unsigned)__cvta_generic_to_shared(Vw);

    int bh = blockIdx.y;
    int b = bh / HH, h = bh % HH;
    int row0 = blockIdx.x * FM;
    const __half* qb  = q  + (size_t)b * SS * EE + h * DD;
    const __half* kb  = k  + (size_t)b * SS * EE + h * DD;
    const __half* vtb = vt + (size_t)bh * DD * SS;

    int tid  = threadIdx.x;
    int warp = tid >> 5, lane = tid & 31;
    int gid  = lane >> 2, tig = lane & 3;
    int arow = lane & 15;
    int acb  = (lane >> 4) * 4;

    #pragma unroll
    for (int i = 0; i < 4; i++) {
        int slot = tid + i * 256;
        int r = slot >> 3, cw = (slot & 7) * 4;
        cp16(sQ + (unsigned)(r * PQW + cw) * 4, qb + (size_t)(row0 + r) * EE + (slot & 7) * 8);
    }
    cp_commit();

    auto load_kv = [&](int st, int k0) {
        #pragma unroll
        for (int i = 0; i < 2; i++) {
            int slot = tid + i * 256;
            int r = slot >> 3, cw = (slot & 7) * 4;
            cp16(sK + (unsigned)((st*FK + r) * PQW + cw) * 4,
                 kb + (size_t)(k0 + r) * EE + (slot & 7) * 8);
        }
        #pragma unroll
        for (int i = 0; i < 2; i++) {
            int slot = tid + i * 256;
            int r = slot >> 3, cw = (slot & 7) * 4;
            cp16(sV + (unsigned)((st*DD + r) * PQW + cw) * 4,
                 vtb + (size_t)r * SS + k0 + (slot & 7) * 8);
        }
        cp_commit();
    };
    load_kv(0, 0);
    load_kv(1, FK);

    cp_wait2();
    __syncthreads();

    int m0r = warp * 16 + gid;
    unsigned qf[4][4];
    #pragma unroll
    for (int kc = 0; kc < 4; kc++) {
        unsigned ad = sQ + (unsigned)((warp*16 + arow) * PQW + kc*8 + acb) * 4;
        ldsm4(qf[kc][0], qf[kc][1], qf[kc][2], qf[kc][3], ad);
    }
    __syncwarp();

    unsigned* Pw = Qw + (warp * 16) * PQW;
    unsigned sP = sQ + (unsigned)(warp * 16 * PQW) * 4;

    float o[8][4];
    #pragma unroll
    for (int ni = 0; ni < 8; ni++)
        #pragma unroll
        for (int r = 0; r < 4; r++) o[ni][r] = 0.0f;
    float mx0 = -1e30f, mx1 = -1e30f, l0 = 0.0f, l1 = 0.0f;
    const float scale = rsqrtf((float)EE);

    const int NIT = SS / FK;   // 32
    for (int it = 0; it < NIT; it++) {
        if (it >= NIT - 2) cp_wait0(); else cp_wait1();
        __syncthreads();
        if (it + 2 < NIT) load_kv((it + 2) % FSTG, (it + 2) * FK);

        int buf = it % FSTG;
        unsigned kBase = sK + (unsigned)(buf * FK * PQW) * 4;
        unsigned vBase = sV + (unsigned)(buf * DD * PQW) * 4;

        // ---- S = Q K^T ----
        float s[8][4];
        #pragma unroll
        for (int ni = 0; ni < 8; ni++)
            #pragma unroll
            for (int r = 0; r < 4; r++) s[ni][r] = 0.0f;

        #pragma unroll
        for (int kc = 0; kc < 4; kc++) {
            int kw = kc * 8;
            unsigned bf[8][2];
            #pragma unroll
            for (int np = 0; np < 4; np++) {
                unsigned bd = kBase + (unsigned)((np*16 + arow) * PQW + kw + acb) * 4;
                ldsm4(bf[2*np][0], bf[2*np+1][0], bf[2*np][1], bf[2*np+1][1], bd);
            }
            #pragma unroll
            for (int ni = 0; ni < 8; ni++)
                mma_f16(s[ni][0], s[ni][1], s[ni][2], s[ni][3],
                        qf[kc][0], qf[kc][1], qf[kc][2], qf[kc][3],
                        bf[ni][0], bf[ni][1]);
        }

        // ---- online softmax ----
        float rm0 = -1e30f, rm1 = -1e30f;
        #pragma unroll
        for (int ni = 0; ni < 8; ni++) {
            s[ni][0] *= scale; s[ni][1] *= scale;
            s[ni][2] *= scale; s[ni][3] *= scale;
            rm0 = fmaxf(rm0, fmaxf(s[ni][0], s[ni][1]));
            rm1 = fmaxf(rm1, fmaxf(s[ni][2], s[ni][3]));
        }
        rm0 = fmaxf(rm0, __shfl_xor_sync(0xffffffffu, rm0, 1));
        rm0 = fmaxf(rm0, __shfl_xor_sync(0xffffffffu, rm0, 2));
        rm1 = fmaxf(rm1, __shfl_xor_sync(0xffffffffu, rm1, 1));
        rm1 = fmaxf(rm1, __shfl_xor_sync(0xffffffffu, rm1, 2));

        float mn0 = fmaxf(mx0, rm0), mn1 = fmaxf(mx1, rm1);
        float f0 = __expf(mx0 - mn0), f1 = __expf(mx1 - mn1);
        mx0 = mn0; mx1 = mn1;

        float rs0 = 0.0f, rs1 = 0.0f;
        #pragma unroll
        for (int ni = 0; ni < 8; ni++) {
            float p0 = __expf(s[ni][0] - mn0);
            float p1 = __expf(s[ni][1] - mn0);
            float p2 = __expf(s[ni][2] - mn1);
            float p3 = __expf(s[ni][3] - mn1);
            rs0 += p0 + p1; rs1 += p2 + p3;
            __half2 h0 = __floats2half2_rn(p0, p1);
            __half2 h1 = __floats2half2_rn(p2, p3);
            Pw[gid * PQW + ni*4 + tig]       = *(unsigned*)&h0;
            Pw[(gid + 8) * PQW + ni*4 + tig] = *(unsigned*)&h1;
        }
        rs0 += __shfl_xor_sync(0xffffffffu, rs0, 1);
        rs0 += __shfl_xor_sync(0xffffffffu, rs0, 2);
        rs1 += __shfl_xor_sync(0xffffffffu, rs1, 1);
        rs1 += __shfl_xor_sync(0xffffffffu, rs1, 2);
        l0 = l0 * f0 + rs0;
        l1 = l1 * f1 + rs1;

        #pragma unroll
        for (int ni = 0; ni < 8; ni++) {
            o[ni][0] *= f0; o[ni][1] *= f0;
            o[ni][2] *= f1; o[ni][3] *= f1;
        }
        __syncwarp();

        // ---- O += P V ----
        #pragma unroll
        for (int kc = 0; kc < 4; kc++) {
            int kw = kc * 8;
            unsigned pa[4];
            unsigned pd = sP + (unsigned)(arow * PQW + kw + acb) * 4;
            ldsm4(pa[0], pa[1], pa[2], pa[3], pd);
            unsigned bf[8][2];
            #pragma unroll
            for (int np = 0; np < 4; np++) {
                unsigned bd = vBase + (unsigned)((np*16 + arow) * PQW + kw + acb) * 4;
                ldsm4(bf[2*np][0], bf[2*np+1][0], bf[2*np][1], bf[2*np+1][1], bd);
            }
            #pragma unroll
            for (int ni = 0; ni < 8; ni++)
                mma_f16(o[ni][0], o[ni][1], o[ni][2], o[ni][3],
                        pa[0], pa[1], pa[2], pa[3],
                        bf[ni][0], bf[ni][1]);
        }
        __syncwarp();
    }

    float i0 = 1.0f / l0, i1 = 1.0f / l1;
    __half2* c0row = (__half2*)(ctx + (size_t)(b * SS + row0 + m0r) * EE + h * DD);
    __half2* c1row = (__half2*)(ctx + (size_t)(b * SS + row0 + m0r + 8) * EE + h * DD);
    #pragma unroll
    for (int ni = 0; ni < 8; ni++) {
        int c2 = (ni * 8 + tig * 2) / 2;
        c0row[c2] = __floats2half2_rn(o[ni][0] * i0, o[ni][1] * i0);
        c1row[c2] = __floats2half2_rn(o[ni][2] * i1, o[ni][3] * i1);
    }
}

// ---------------- launch ------------------------------------------------------------
extern "C" void kernel_launch(void* const* d_in, const int* in_sizes, int n_in,
                              void* d_out, int out_size) {
    (void)in_sizes; (void)n_in; (void)out_size;
    const float* x     = (const float*)d_in[0];
    const float* ln1_g = (const float*)d_in[1];
    const float* ln1_b = (const float*)d_in[2];
    const float* wq    = (const float*)d_in[3];
    const float* bq    = (const float*)d_in[4];
    const float* wk    = (const float*)d_in[5];
    const float* bk    = (const float*)d_in[6];
    const float* wv    = (const float*)d_in[7];
    const float* bv    = (const float*)d_in[8];
    const float* wo    = (const float*)d_in[9];
    const float* bo    = (const float*)d_in[10];
    const float* w1    = (const float*)d_in[11];
    const float* b1    = (const float*)d_in[12];
    const float* w2    = (const float*)d_in[13];
    const float* b2    = (const float*)d_in[14];
    const float* ln2_g = (const float*)d_in[15];
    const float* ln2_b = (const float*)d_in[16];
    float* out = (float*)d_out;

    __half *y, *q, *k, *v, *vt, *ctx, *z, *hbuf;
    float *y2;
    __half *wtq, *wtk, *wtv, *wto, *wt1, *wt2;
    cudaGetSymbolAddress((void**)&y,    g_y);
    cudaGetSymbolAddress((void**)&q,    g_q);
    cudaGetSymbolAddress((void**)&k,    g_k);
    cudaGetSymbolAddress((void**)&v,    g_v);
    cudaGetSymbolAddress((void**)&vt,   g_vt);
    cudaGetSymbolAddress((void**)&ctx,  g_ctx);
    cudaGetSymbolAddress((void**)&y2,   g_y2);
    cudaGetSymbolAddress((void**)&z,    g_z);
    cudaGetSymbolAddress((void**)&hbuf, g_h);
    cudaGetSymbolAddress((void**)&wtq,  g_wtq);
    cudaGetSymbolAddress((void**)&wtk,  g_wtk);
    cudaGetSymbolAddress((void**)&wtv,  g_wtv);
    cudaGetSymbolAddress((void**)&wto,  g_wto);
    cudaGetSymbolAddress((void**)&wt1,  g_wt1);
    cudaGetSymbolAddress((void**)&wt2,  g_wt2);

    static bool attr_done = false;
    if (!attr_done) {
        cudaFuncSetAttribute((const void*)mmh_tc<false,true,false>,
                             cudaFuncAttributeMaxDynamicSharedMemorySize, SM_MMH);
        cudaFuncSetAttribute((const void*)mmh_tc<true,false,true>,
                             cudaFuncAttributeMaxDynamicSharedMemorySize, SM_MMH);
        cudaFuncSetAttribute((const void*)qkvh_tc,
                             cudaFuncAttributeMaxDynamicSharedMemorySize, SM_MMH);
        cudaFuncSetAttribute((const void*)flash_h,
                             cudaFuncAttributeMaxDynamicSharedMemorySize, SM_FLASH);
        attr_done = true;
    }

    dim3 blk128(128);
    dim3 blk256(256);
    dim3 tb(32, 8);

    // 0. convert+transpose weights
    cvt_t4<<<dim3(EE/32, EE/32, 4), tb>>>(wq, wtq, wk, wtk, wv, wtv, wo, wto);
    cvt_tff<<<dim3(FF/32, FF/32, 2), tb>>>(w1, wt1, w2, wt2);

    // 1. y = LN1(x)
    ln_kernel<<<MM, blk256>>>(x, ln1_g, ln1_b, y);

    // 2. q,k,v projections
    dim3 g_qkv(EE / 128, MM / 64, 3);
    qkvh_tc<<<g_qkv, blk128, SM_MMH>>>(y, wtq, bq, q, wtk, bk, k, wtv, bv, v);

    // 2b. transpose V per head
    vtrans<<<dim3(SS/32, DD/32, BH), tb>>>(v, vt);

    // 3. flash attention
    dim3 g_fl(SS / FM, BH);
    flash_h<<<g_fl, blk256, SM_FLASH>>>(q, k, vt, ctx);

    // 4. y2 = x + ctx @ wo + bo
    dim3 g_e(EE / 128, MM / 64);
    mmh_tc<false, true, false><<<g_e, blk128, SM_MMH>>>(ctx, wto, bo, x, y2, EE, EE);

    // 5. z = LN2(y2)
    ln_kernel<<<MM, blk256>>>(y2, ln2_g, ln2_b, z);

    // 6. h = gelu(z @ w1 + b1)
    dim3 g_ff(FF / 128, MM / 64);
    mmh_tc<true, false, true><<<g_ff, blk128, SM_MMH>>>(z, wt1, b1, nullptr, hbuf, FF, EE);

    // 7. out = y2 + h @ w2 + b2
    mmh_tc<false, true, false><<<g_e, blk128, SM_MMH>>>(hbuf, wt2, b2, y2, out, EE, FF);
}

// round 16
// speedup vs baseline: 1.0315x; 1.0315x over previous
#include <cuda_runtime.h>
#include <cuda_fp16.h>
#include <math.h>

#define BB 2
#define SS 2048
#define EE 768
#define HH 12
#define DD 64
#define MM (BB*SS)      /* 4096 rows */
#define FF (4*EE)       /* 3072 */
#define BH (BB*HH)      /* 24 */

#define BK 64           /* k halves per GEMM slab */
#define PAW 36          /* GEMM [row][k] pitch in half2 words */

/* flash (fp16) tiles */
#define FM 128
#define FK 64
#define PQW 36
#define FSTG 3

// dynamic smem sizes (bytes)
#define SM_MMH   (2*(64*PAW + 128*PAW)*4)                  /* 55296 */
#define SM_FLASH ((128*PQW + FSTG*FK*PQW + FSTG*FK*PQW)*4) /* 73728 */

// ---------------- scratch (device globals; no allocation allowed) ----------------
__device__ __half g_y  [MM*EE];
__device__ __half g_q  [MM*EE];
__device__ __half g_k  [MM*EE];
__device__ __half g_v  [MM*EE];
__device__ __half g_vt [BH*DD*SS];
__device__ __half g_ctx[MM*EE];
__device__ float  g_y2 [MM*EE];
__device__ __half g_z  [MM*EE];
__device__ __half g_h  [MM*FF];
__device__ __half g_wtq[EE*EE];
__device__ __half g_wtk[EE*EE];
__device__ __half g_wtv[EE*EE];
__device__ __half g_wto[EE*EE];
__device__ __half g_wt1[FF*EE];
__device__ __half g_wt2[EE*FF];

// ---------------- helpers ---------------------------------------------------------
__device__ __forceinline__ void mma_f16(float& c0, float& c1, float& c2, float& c3,
                                        unsigned a0, unsigned a1, unsigned a2, unsigned a3,
                                        unsigned b0, unsigned b1) {
    asm volatile(
        "mma.sync.aligned.m16n8k16.row.col.f32.f16.f16.f32 "
        "{%0,%1,%2,%3}, {%4,%5,%6,%7}, {%8,%9}, {%0,%1,%2,%3};"
        : "+f"(c0), "+f"(c1), "+f"(c2), "+f"(c3)
        : "r"(a0), "r"(a1), "r"(a2), "r"(a3), "r"(b0), "r"(b1));
}

__device__ __forceinline__ void cp16(unsigned saddr, const void* g) {
    asm volatile("cp.async.cg.shared.global [%0], [%1], 16;" :: "r"(saddr), "l"(g));
}
__device__ __forceinline__ void cp_commit() { asm volatile("cp.async.commit_group;"); }
__device__ __forceinline__ void cp_wait0()  { asm volatile("cp.async.wait_group 0;"); }
__device__ __forceinline__ void cp_wait1()  { asm volatile("cp.async.wait_group 1;"); }
__device__ __forceinline__ void cp_wait2()  { asm volatile("cp.async.wait_group 2;"); }

// ---------------- weight convert + transpose --------------------------------------
__global__ void cvt_t4(const float* __restrict__ s0, __half* __restrict__ d0,
                       const float* __restrict__ s1, __half* __restrict__ d1,
                       const float* __restrict__ s2, __half* __restrict__ d2,
                       const float* __restrict__ s3, __half* __restrict__ d3) {
    __shared__ float t[32][33];
    const float* src; __half* dst;
    if (blockIdx.z == 0)      { src = s0; dst = d0; }
    else if (blockIdx.z == 1) { src = s1; dst = d1; }
    else if (blockIdx.z == 2) { src = s2; dst = d2; }
    else                      { src = s3; dst = d3; }
    int bx = blockIdx.x * 32;
    int by = blockIdx.y * 32;
    int x = threadIdx.x, y0 = threadIdx.y;
    #pragma unroll
    for (int i = 0; i < 32; i += 8)
        t[y0 + i][x] = src[(size_t)(by + y0 + i) * EE + bx + x];
    __syncthreads();
    #pragma unroll
    for (int i = 0; i < 32; i += 8)
        dst[(size_t)(bx + y0 + i) * EE + by + x] = __float2half(t[x][y0 + i]);
}

__global__ void cvt_tff(const float* __restrict__ w1, __half* __restrict__ wt1,
                        const float* __restrict__ w2, __half* __restrict__ wt2) {
    __shared__ float t[32][33];
    const float* src; __half* dst; int R, C;
    if (blockIdx.z == 0) { src = w1; dst = wt1; R = EE; C = FF; }
    else                 { src = w2; dst = wt2; R = FF; C = EE; }
    int bx = blockIdx.x * 32;
    int by = blockIdx.y * 32;
    if (bx >= C || by >= R) return;
    int x = threadIdx.x, y0 = threadIdx.y;
    #pragma unroll
    for (int i = 0; i < 32; i += 8)
        t[y0 + i][x] = src[(size_t)(by + y0 + i) * C + bx + x];
    __syncthreads();
    #pragma unroll
    for (int i = 0; i < 32; i += 8)
        dst[(size_t)(bx + y0 + i) * R + by + x] = __float2half(t[x][y0 + i]);
}

// ---------------- V transpose per head ---------------------------------------------
__global__ void vtrans(const __half* __restrict__ v, __half* __restrict__ vt) {
    __shared__ __half t[32][33];
    int bh = blockIdx.z;
    int b = bh / HH, h = bh % HH;
    int s0 = blockIdx.x * 32;
    int d0 = blockIdx.y * 32;
    int x = threadIdx.x, y0 = threadIdx.y;
    #pragma unroll
    for (int i = 0; i < 32; i += 8)
        t[y0 + i][x] = v[(size_t)(b * SS + s0 + y0 + i) * EE + h * DD + d0 + x];
    __syncthreads();
    #pragma unroll
    for (int i = 0; i < 32; i += 8)
        vt[(size_t)bh * DD * SS + (size_t)(d0 + y0 + i) * SS + s0 + x] = t[x][y0 + i];
}

// ---------------- LayerNorm ---------------------------------------------------------
__global__ void ln_kernel(const float* __restrict__ x, const float* __restrict__ gw,
                          const float* __restrict__ bw, __half* __restrict__ out) {
    int row = blockIdx.x;
    int t = threadIdx.x;
    int warp = t >> 5, lane = t & 31;
    __shared__ float ws1[8], ws2[8], bc[2];

    float4 xv = make_float4(0.f, 0.f, 0.f, 0.f);
    if (t < 192)
        xv = *(const float4*)(x + (size_t)row * EE + t * 4);
    float s1 = xv.x + xv.y + xv.z + xv.w;
    float s2 = xv.x*xv.x + xv.y*xv.y + xv.z*xv.z + xv.w*xv.w;
    #pragma unroll
    for (int o = 16; o > 0; o >>= 1) {
        s1 += __shfl_xor_sync(0xffffffffu, s1, o);
        s2 += __shfl_xor_sync(0xffffffffu, s2, o);
    }
    if (lane == 0) { ws1[warp] = s1; ws2[warp] = s2; }
    __syncthreads();
    if (t == 0) {
        float a = 0.f, b = 0.f;
        #pragma unroll
        for (int i = 0; i < 8; i++) { a += ws1[i]; b += ws2[i]; }
        float mean = a * (1.0f / EE);
        float var  = b * (1.0f / EE) - mean * mean;
        bc[0] = mean;
        bc[1] = rsqrtf(var + 1e-5f);
    }
    __syncthreads();
    if (t < 192) {
        float mean = bc[0], rstd = bc[1];
        float4 gv = *(const float4*)(gw + t * 4);
        float4 bv = *(const float4*)(bw + t * 4);
        float o0 = (xv.x - mean) * rstd * gv.x + bv.x;
        float o1 = (xv.y - mean) * rstd * gv.y + bv.y;
        float o2 = (xv.z - mean) * rstd * gv.z + bv.z;
        float o3 = (xv.w - mean) * rstd * gv.w + bv.w;
        __half2 h0 = __floats2half2_rn(o0, o1);
        __half2 h1 = __floats2half2_rn(o2, o3);
        uint2 pk; pk.x = *(unsigned*)&h0; pk.y = *(unsigned*)&h1;
        *(uint2*)(out + (size_t)row * EE + t * 4) = pk;
    }
}

// ---------------- fp16 GEMM core 64x128 CTA, 4 warps (2x2), warp tile 32x64 -------
// BK=64, scalar LDS fragments (R14 core), 4 CTAs/SM via launch_bounds.
template<bool GELU, bool RES, bool OUTH>
__device__ __forceinline__ void
mmh_body(const __half* __restrict__ A, const __half* __restrict__ Wt,
         const float* __restrict__ bias, const float* __restrict__ res,
         void* __restrict__ Cv, int N, int K, int row0, int col0, char* smem) {
    unsigned* As_ = (unsigned*)smem;                  // [2][64][PAW]
    unsigned* Bs_ = As_ + 2 * 64 * PAW;               // [2][128][PAW]
    unsigned sA = (unsigned)__cvta_generic_to_shared(As_);
    unsigned sB = (unsigned)__cvta_generic_to_shared(Bs_);

    int tid  = threadIdx.x;
    int warp = tid >> 5, lane = tid & 31;
    int gid  = lane >> 2, tig = lane & 3;
    int wm   = warp & 1;
    int wn   = warp >> 1;

    float acc[2][8][4];
    #pragma unroll
    for (int i = 0; i < 2; i++)
        #pragma unroll
        for (int j = 0; j < 8; j++)
            #pragma unroll
            for (int r = 0; r < 4; r++) acc[i][j][r] = 0.0f;

    int NIT = K / BK;

    auto load_st = [&](int st, int k0) {
        #pragma unroll
        for (int i = 0; i < 4; i++) {
            int slot = tid + i * 128;
            int r = slot >> 3, c = slot & 7;
            cp16(sA + (unsigned)((st*64 + r)*PAW + c * 4)*4,
                 A + (size_t)(row0 + r) * K + k0 + c * 8);
        }
        #pragma unroll
        for (int i = 0; i < 8; i++) {
            int slot = tid + i * 128;
            int r = slot >> 3, c = slot & 7;
            cp16(sB + (unsigned)((st*128 + r)*PAW + c * 4)*4,
                 Wt + (size_t)(col0 + r) * K + k0 + c * 8);
        }
        cp_commit();
    };

    load_st(0, 0);

    for (int it = 0; it < NIT; it++) {
        cp_wait0();
        __syncthreads();

        if (it + 1 < NIT) load_st((it + 1) & 1, (it + 1) * BK);

        int buf = it & 1;
        const unsigned* Ab = As_ + buf * 64 * PAW;
        const unsigned* Bb = Bs_ + buf * 128 * PAW;

        #pragma unroll
        for (int kk2 = 0; kk2 < 4; kk2++) {
            int kw = kk2 * 8;
            unsigned af[2][4], bf[8][2];
            #pragma unroll
            for (int mi = 0; mi < 2; mi++) {
                int m = wm * 32 + mi * 16 + gid;
                af[mi][0] = Ab[m * PAW + kw + tig];
                af[mi][1] = Ab[(m + 8) * PAW + kw + tig];
                af[mi][2] = Ab[m * PAW + kw + tig + 4];
                af[mi][3] = Ab[(m + 8) * PAW + kw + tig + 4];
            }
            #pragma unroll
            for (int ni = 0; ni < 8; ni++) {
                int n = wn * 64 + ni * 8 + gid;
                bf[ni][0] = Bb[n * PAW + kw + tig];
                bf[ni][1] = Bb[n * PAW + kw + tig + 4];
            }
            #pragma unroll
            for (int mi = 0; mi < 2; mi++)
                #pragma unroll
                for (int ni = 0; ni < 8; ni++)
                    mma_f16(acc[mi][ni][0], acc[mi][ni][1], acc[mi][ni][2], acc[mi][ni][3],
                            af[mi][0], af[mi][1], af[mi][2], af[mi][3],
                            bf[ni][0], bf[ni][1]);
        }
    }

    #pragma unroll
    for (int mi = 0; mi < 2; mi++) {
        int r0 = row0 + wm * 32 + mi * 16 + gid;
        int r1 = r0 + 8;
        #pragma unroll
        for (int ni = 0; ni < 8; ni++) {
            int c = col0 + wn * 64 + ni * 8 + tig * 2;
            float2 b2 = *(const float2*)(bias + c);
            float v00 = acc[mi][ni][0] + b2.x;
            float v01 = acc[mi][ni][1] + b2.y;
            float v10 = acc[mi][ni][2] + b2.x;
            float v11 = acc[mi][ni][3] + b2.y;
            if (RES) {
                float2 e0 = *(const float2*)(res + (size_t)r0 * N + c);
                float2 e1 = *(const float2*)(res + (size_t)r1 * N + c);
                v00 += e0.x; v01 += e0.y; v10 += e1.x; v11 += e1.y;
            }
            if (GELU) {
                v00 = v00 * 0.5f * (1.0f + erff(v00 * 0.70710678118654752f));
                v01 = v01 * 0.5f * (1.0f + erff(v01 * 0.70710678118654752f));
                v10 = v10 * 0.5f * (1.0f + erff(v10 * 0.70710678118654752f));
                v11 = v11 * 0.5f * (1.0f + erff(v11 * 0.70710678118654752f));
            }
            if (OUTH) {
                __half2* C = (__half2*)Cv;
                C[((size_t)r0 * N + c) / 2] = __floats2half2_rn(v00, v01);
                C[((size_t)r1 * N + c) / 2] = __floats2half2_rn(v10, v11);
            } else {
                float* C = (float*)Cv;
                *(float2*)(C + (size_t)r0 * N + c) = make_float2(v00, v01);
                *(float2*)(C + (size_t)r1 * N + c) = make_float2(v10, v11);
            }
        }
    }
}

template<bool GELU, bool RES, bool OUTH>
__global__ void __launch_bounds__(128, 4)
mmh_tc(const __half* __restrict__ A, const __half* __restrict__ Wt,
       const float* __restrict__ bias, const float* __restrict__ res,
       void* __restrict__ C, int N, int K) {
    extern __shared__ char smem[];
    mmh_body<GELU, RES, OUTH>(A, Wt, bias, res, C, N, K,
                              blockIdx.y * 64, blockIdx.x * 128, smem);
}

__global__ void __launch_bounds__(128, 4)
qkvh_tc(const __half* __restrict__ y,
        const __half* __restrict__ wtq, const float* __restrict__ bq, __half* __restrict__ q,
        const __half* __restrict__ wtk, const float* __restrict__ bk, __half* __restrict__ k,
        const __half* __restrict__ wtv, const float* __restrict__ bv, __half* __restrict__ v) {
    extern __shared__ char smem[];
    const __half* Wt; const float* bias; __half* C;
    if (blockIdx.z == 0)      { Wt = wtq; bias = bq; C = q; }
    else if (blockIdx.z == 1) { Wt = wtk; bias = bk; C = k; }
    else                      { Wt = wtv; bias = bv; C = v; }
    mmh_body<false, false, true>(y, Wt, bias, nullptr, C, EE, EE,
                                 blockIdx.y * 64, blockIdx.x * 128, smem);
}

// ---------------- Flash attention, fp16 MMA (R14/R13 core) -------------------------
__global__ void __launch_bounds__(256, 2)
flash_h(const __half* __restrict__ q, const __half* __restrict__ k,
        const __half* __restrict__ vt, __half* __restrict__ ctx) {
    extern __shared__ char smem[];
    unsigned* Qw = (unsigned*)smem;
    unsigned* Kw = Qw + 128 * PQW;
    unsigned* Vw = Kw + FSTG * FK * PQW;
    unsigned sQ = (unsigned)__cvta_generic_to_shared(Qw);
    unsigned sK = (unsigned)__cvta_generic_to_shared(Kw);
    unsigned sV = (unsigned)__cvta_generic_to_shared(Vw);

    int bh = blockIdx.y;
    int b = bh / HH, h = bh % HH;
    int row0 = blockIdx.x * FM;
    const __half* qb  = q  + (size_t)b * SS * EE + h * DD;
    const __half* kb  = k  + (size_t)b * SS * EE + h * DD;
    const __half* vtb = vt + (size_t)bh * DD * SS;

    int tid  = threadIdx.x;
    int warp = tid >> 5, lane = tid & 31;
    int gid  = lane >> 2, tig = lane & 3;

    #pragma unroll
    for (int i = 0; i < 4; i++) {
        int slot = tid + i * 256;
        int r = slot >> 3, cw = (slot & 7) * 4;
        cp16(sQ + (unsigned)(r * PQW + cw) * 4, qb + (size_t)(row0 + r) * EE + (slot & 7) * 8);
    }
    cp_commit();

    auto load_kv = [&](int st, int k0) {
        #pragma unroll
        for (int i = 0; i < 2; i++) {
            int slot = tid + i * 256;
            int r = slot >> 3, cw = (slot & 7) * 4;
            cp16(sK + (unsigned)((st*FK + r) * PQW + cw) * 4,
                 kb + (size_t)(k0 + r) * EE + (slot & 7) * 8);
        }
        #pragma unroll
        for (int i = 0; i < 2; i++) {
            int slot = tid + i * 256;
            int r = slot >> 3, cw = (slot & 7) * 4;
            cp16(sV + (unsigned)((st*DD + r) * PQW + cw) * 4,
                 vtb + (size_t)r * SS + k0 + (slot & 7) * 8);
        }
        cp_commit();
    };
    load_kv(0, 0);
    load_kv(1, FK);

    cp_wait2();
    __syncthreads();

    int m0r = warp * 16 + gid;
    unsigned qf[4][4];
    #pragma unroll
    for (int kc = 0; kc < 4; kc++) {
        qf[kc][0] = Qw[m0r * PQW + kc*8 + tig];
        qf[kc][1] = Qw[(m0r + 8) * PQW + kc*8 + tig];
        qf[kc][2] = Qw[m0r * PQW + kc*8 + tig + 4];
        qf[kc][3] = Qw[(m0r + 8) * PQW + kc*8 + tig + 4];
    }
    __syncwarp();

    unsigned* Pw = Qw + (warp * 16) * PQW;

    float o[8][4];
    #pragma unroll
    for (int ni = 0; ni < 8; ni++)
        #pragma unroll
        for (int r = 0; r < 4; r++) o[ni][r] = 0.0f;
    float mx0 = -1e30f, mx1 = -1e30f, l0 = 0.0f, l1 = 0.0f;
    const float scale = rsqrtf((float)EE);

    const int NIT = SS / FK;   // 32
    for (int it = 0; it < NIT; it++) {
        if (it >= NIT - 2) cp_wait0(); else cp_wait1();
        __syncthreads();
        if (it + 2 < NIT) load_kv((it + 2) % FSTG, (it + 2) * FK);

        int buf = it % FSTG;
        const unsigned* Kb = Kw + buf * FK * PQW;
        const unsigned* Vb = Vw + buf * DD * PQW;

        float s[8][4];
        #pragma unroll
        for (int ni = 0; ni < 8; ni++)
            #pragma unroll
            for (int r = 0; r < 4; r++) s[ni][r] = 0.0f;

        #pragma unroll
        for (int kc = 0; kc < 4; kc++) {
            #pragma unroll
            for (int ni = 0; ni < 8; ni++) {
                int n = ni * 8 + gid;
                unsigned b0 = Kb[n * PQW + kc*8 + tig];
                unsigned b1 = Kb[n * PQW + kc*8 + tig + 4];
                mma_f16(s[ni][0], s[ni][1], s[ni][2], s[ni][3],
                        qf[kc][0], qf[kc][1], qf[kc][2], qf[kc][3], b0, b1);
            }
        }

        float rm0 = -1e30f, rm1 = -1e30f;
        #pragma unroll
        for (int ni = 0; ni < 8; ni++) {
            s[ni][0] *= scale; s[ni][1] *= scale;
            s[ni][2] *= scale; s[ni][3] *= scale;
            rm0 = fmaxf(rm0, fmaxf(s[ni][0], s[ni][1]));
            rm1 = fmaxf(rm1, fmaxf(s[ni][2], s[ni][3]));
        }
        rm0 = fmaxf(rm0, __shfl_xor_sync(0xffffffffu, rm0, 1));
        rm0 = fmaxf(rm0, __shfl_xor_sync(0xffffffffu, rm0, 2));
        rm1 = fmaxf(rm1, __shfl_xor_sync(0xffffffffu, rm1, 1));
        rm1 = fmaxf(rm1, __shfl_xor_sync(0xffffffffu, rm1, 2));

        float mn0 = fmaxf(mx0, rm0), mn1 = fmaxf(mx1, rm1);
        float f0 = __expf(mx0 - mn0), f1 = __expf(mx1 - mn1);
        mx0 = mn0; mx1 = mn1;

        float rs0 = 0.0f, rs1 = 0.0f;
        #pragma unroll
        for (int ni = 0; ni < 8; ni++) {
            float p0 = __expf(s[ni][0] - mn0);
            float p1 = __expf(s[ni][1] - mn0);
            float p2 = __expf(s[ni][2] - mn1);
            float p3 = __expf(s[ni][3] - mn1);
            rs0 += p0 + p1; rs1 += p2 + p3;
            __half2 h0 = __floats2half2_rn(p0, p1);
            __half2 h1 = __floats2half2_rn(p2, p3);
            Pw[gid * PQW + ni*4 + tig]       = *(unsigned*)&h0;
            Pw[(gid + 8) * PQW + ni*4 + tig] = *(unsigned*)&h1;
        }
        rs0 += __shfl_xor_sync(0xffffffffu, rs0, 1);
        rs0 += __shfl_xor_sync(0xffffffffu, rs0, 2);
        rs1 += __shfl_xor_sync(0xffffffffu, rs1, 1);
        rs1 += __shfl_xor_sync(0xffffffffu, rs1, 2);
        l0 = l0 * f0 + rs0;
        l1 = l1 * f1 + rs1;

        #pragma unroll
        for (int ni = 0; ni < 8; ni++) {
            o[ni][0] *= f0; o[ni][1] *= f0;
            o[ni][2] *= f1; o[ni][3] *= f1;
        }
        __syncwarp();

        #pragma unroll
        for (int kc = 0; kc < 4; kc++) {
            unsigned a0 = Pw[gid * PQW + kc*8 + tig];
            unsigned a1 = Pw[(gid + 8) * PQW + kc*8 + tig];
            unsigned a2 = Pw[gid * PQW + kc*8 + tig + 4];
            unsigned a3 = Pw[(gid + 8) * PQW + kc*8 + tig + 4];
            #pragma unroll
            for (int ni = 0; ni < 8; ni++) {
                int n = ni * 8 + gid;
                unsigned b0 = Vb[n * PQW + kc*8 + tig];
                unsigned b1 = Vb[n * PQW + kc*8 + tig + 4];
                mma_f16(o[ni][0], o[ni][1], o[ni][2], o[ni][3],
                        a0, a1, a2, a3, b0, b1);
            }
        }
        __syncwarp();
    }

    float i0 = 1.0f / l0, i1 = 1.0f / l1;
    __half2* c0row = (__half2*)(ctx + (size_t)(b * SS + row0 + m0r) * EE + h * DD);
    __half2* c1row = (__half2*)(ctx + (size_t)(b * SS + row0 + m0r + 8) * EE + h * DD);
    #pragma unroll
    for (int ni = 0; ni < 8; ni++) {
        int c2 = (ni * 8 + tig * 2) / 2;
        c0row[c2] = __floats2half2_rn(o[ni][0] * i0, o[ni][1] * i0);
        c1row[c2] = __floats2half2_rn(o[ni][2] * i1, o[ni][3] * i1);
    }
}

// ---------------- launch ------------------------------------------------------------
extern "C" void kernel_launch(void* const* d_in, const int* in_sizes, int n_in,
                              void* d_out, int out_size) {
    (void)in_sizes; (void)n_in; (void)out_size;
    const float* x     = (const float*)d_in[0];
    const float* ln1_g = (const float*)d_in[1];
    const float* ln1_b = (const float*)d_in[2];
    const float* wq    = (const float*)d_in[3];
    const float* bq    = (const float*)d_in[4];
    const float* wk    = (const float*)d_in[5];
    const float* bk    = (const float*)d_in[6];
    const float* wv    = (const float*)d_in[7];
    const float* bv    = (const float*)d_in[8];
    const float* wo    = (const float*)d_in[9];
    const float* bo    = (const float*)d_in[10];
    const float* w1    = (const float*)d_in[11];
    const float* b1    = (const float*)d_in[12];
    const float* w2    = (const float*)d_in[13];
    const float* b2    = (const float*)d_in[14];
    const float* ln2_g = (const float*)d_in[15];
    const float* ln2_b = (const float*)d_in[16];
    float* out = (float*)d_out;

    __half *y, *q, *k, *v, *vt, *ctx, *z, *hbuf;
    float *y2;
    __half *wtq, *wtk, *wtv, *wto, *wt1, *wt2;
    cudaGetSymbolAddress((void**)&y,    g_y);
    cudaGetSymbolAddress((void**)&q,    g_q);
    cudaGetSymbolAddress((void**)&k,    g_k);
    cudaGetSymbolAddress((void**)&v,    g_v);
    cudaGetSymbolAddress((void**)&vt,   g_vt);
    cudaGetSymbolAddress((void**)&ctx,  g_ctx);
    cudaGetSymbolAddress((void**)&y2,   g_y2);
    cudaGetSymbolAddress((void**)&z,    g_z);
    cudaGetSymbolAddress((void**)&hbuf, g_h);
    cudaGetSymbolAddress((void**)&wtq,  g_wtq);
    cudaGetSymbolAddress((void**)&wtk,  g_wtk);
    cudaGetSymbolAddress((void**)&wtv,  g_wtv);
    cudaGetSymbolAddress((void**)&wto,  g_wto);
    cudaGetSymbolAddress((void**)&wt1,  g_wt1);
    cudaGetSymbolAddress((void**)&wt2,  g_wt2);

    static bool attr_done = false;
    if (!attr_done) {
        cudaFuncSetAttribute((const void*)mmh_tc<false,true,false>,
                             cudaFuncAttributeMaxDynamicSharedMemorySize, SM_MMH);
        cudaFuncSetAttribute((const void*)mmh_tc<true,false,true>,
                             cudaFuncAttributeMaxDynamicSharedMemorySize, SM_MMH);
        cudaFuncSetAttribute((const void*)qkvh_tc,
                             cudaFuncAttributeMaxDynamicSharedMemorySize, SM_MMH);
        cudaFuncSetAttribute((const void*)flash_h,
                             cudaFuncAttributeMaxDynamicSharedMemorySize, SM_FLASH);
        attr_done = true;
    }

    dim3 blk128(128);
    dim3 blk256(256);
    dim3 tb(32, 8);

    // 0. convert+transpose weights
    cvt_t4<<<dim3(EE/32, EE/32, 4), tb>>>(wq, wtq, wk, wtk, wv, wtv, wo, wto);
    cvt_tff<<<dim3(FF/32, FF/32, 2), tb>>>(w1, wt1, w2, wt2);

    // 1. y = LN1(x)
    ln_kernel<<<MM, blk256>>>(x, ln1_g, ln1_b, y);

    // 2. q,k,v projections
    dim3 g_qkv(EE / 128, MM / 64, 3);
    qkvh_tc<<<g_qkv, blk128, SM_MMH>>>(y, wtq, bq, q, wtk, bk, k, wtv, bv, v);

    // 2b. transpose V per head
    vtrans<<<dim3(SS/32, DD/32, BH), tb>>>(v, vt);

    // 3. flash attention
    dim3 g_fl(SS / FM, BH);
    flash_h<<<g_fl, blk256, SM_FLASH>>>(q, k, vt, ctx);

    // 4. y2 = x + ctx @ wo + bo
    dim3 g_e(EE / 128, MM / 64);
    mmh_tc<false, true, false><<<g_e, blk128, SM_MMH>>>(ctx, wto, bo, x, y2, EE, EE);

    // 5. z = LN2(y2)
    ln_kernel<<<MM, blk256>>>(y2, ln2_g, ln2_b, z);

    // 6. h = gelu(z @ w1 + b1)
    dim3 g_ff(FF / 128, MM / 64);
    mmh_tc<true, false, true><<<g_ff, blk128, SM_MMH>>>(z, wt1, b1, nullptr, hbuf, FF, EE);

    // 7. out = y2 + h @ w2 + b2
    mmh_tc<false, true, false><<<g_e, blk128, SM_MMH>>>(hbuf, wt2, b2, y2, out, EE, FF);
}